// round 6
// baseline (speedup 1.0000x reference)
#include <cuda_runtime.h>
#include <cuda_bf16.h>
#include <cstdint>

#define N_USERS 200000
#define N_MOVIES 80000
#define NN 280000            // N_USERS + N_MOVIES
#define NPAD (NN + 128)      // padded rows so the ragged last combine block is in-bounds
#define H 64
#define FM 20

typedef unsigned long long ull;

// Scratch (device globals; allocation is forbidden). ~220 MB total.
__device__ float g_x0[(size_t)NPAD * H];
__device__ float g_x1[(size_t)NPAD * H];
__device__ float g_agg[(size_t)NPAD * H];
__device__ float g_deg[NPAD];

// ---------------- f32x2 packed-FMA helpers (Blackwell FFMA2) ----------------
__device__ __forceinline__ ull pack2(float a, float b) {
    ull r;
    asm("mov.b64 %0, {%1, %2};" : "=l"(r) : "f"(a), "f"(b));
    return r;
}
__device__ __forceinline__ void fma2(ull& d, ull a, ull b) {
    asm("fma.rn.f32x2 %0, %1, %2, %0;" : "+l"(d) : "l"(a), "l"(b));
}
__device__ __forceinline__ float2 unpack2(ull v) {
    float2 f;
    asm("mov.b64 {%0, %1}, %2;" : "=f"(f.x), "=f"(f.y) : "l"(v));
    return f;
}

// ---------------- movie feature init: x_movie = movie_x @ lin_W.T + lin_b + movie_emb ----
__global__ void movie_init_kernel(const float* __restrict__ movie_x,
                                  const float* __restrict__ lin_W,
                                  const float* __restrict__ lin_b,
                                  const float* __restrict__ movie_emb,
                                  float* __restrict__ x0) {
    int mlocal = threadIdx.x >> 6;
    int h = threadIdx.x & 63;
    int m = blockIdx.x * 4 + mlocal;
    __shared__ float mx[4][FM];
    int li = threadIdx.x;
    if (li < 4 * FM) {
        int mm = li / FM, ff = li % FM;
        mx[mm][ff] = movie_x[(size_t)(blockIdx.x * 4 + mm) * FM + ff];
    }
    __syncthreads();
    float s = lin_b[h];
#pragma unroll
    for (int f = 0; f < FM; f++) s += mx[mlocal][f] * lin_W[h * FM + f];
    x0[(size_t)(N_USERS + m) * H + h] = s + movie_emb[(size_t)m * H + h];
}

// ---------------- degree count (same for both layers) ----------------
__global__ void deg_kernel(const int* __restrict__ dst, float* __restrict__ deg, int E) {
    int e = blockIdx.x * blockDim.x + threadIdx.x;
    if (e < E) atomicAdd(deg + dst[e], 1.0f);
}

// ---------------- scatter: agg[dst] += x[src], vec4 global reductions ----------------
__global__ void scatter_kernel(const int* __restrict__ src,
                               const int* __restrict__ dst,
                               const float* __restrict__ x,
                               float* __restrict__ agg, int E) {
    long long t = (long long)blockIdx.x * blockDim.x + threadIdx.x;
    int e = (int)(t >> 4);
    if (e >= E) return;
    int part = (int)t & 15;
    int s = src[e];
    int d = dst[e];
    float4 v = *reinterpret_cast<const float4*>(x + (size_t)s * H + part * 4);
    float* p = agg + (size_t)d * H + part * 4;
    asm volatile("red.global.add.v4.f32 [%0], {%1,%2,%3,%4};"
                 :: "l"(p), "f"(v.x), "f"(v.y), "f"(v.z), "f"(v.w)
                 : "memory");
}

// ---------------- combine: xout = act( [agg/deg | xin] @ [Wl;Wr]^T + b ) ----------------
// Block: 128 rows x 64 cols (all of H), K=128. 256 threads, 8x4 thread tile.
// Inner loop: A vectorized over k (LDS.128), B pairs loaded as aligned b64 (no packing),
// f32x2 FMAs so fma-pipe (rt=2) and alu-pipe (broadcast MOVs) interleave.
// ZERO: re-zero agg rows after reading (prepares next scatter).
#define COMB_ROWS 128
#define COMB_SMEM_FLOATS (COMB_ROWS * 128 + 128 * 64 + 64)
template <bool RELU, bool ZERO>
__global__ void __launch_bounds__(256, 2)
combine_kernel(const float* __restrict__ xin,
               float* agg,
               const float* __restrict__ deg,
               const float* __restrict__ Wl,
               const float* __restrict__ bias,
               const float* __restrict__ Wr,
               float* __restrict__ xout) {
    extern __shared__ float sh[];
    float* As = sh;                       // [128 rows][128 k]
    float* Bs = sh + COMB_ROWS * 128;     // [128 k][64 h]
    float* Bb = Bs + 128 * 64;            // bias[64]
    int t = threadIdx.x;
    int rowBase = blockIdx.x * COMB_ROWS;

    // Load B = [Wl ; Wr] transposed into Bs[k][h]. Conflict-free: within a warp
    // h is consecutive so each STS hits 32 distinct banks.
#pragma unroll
    for (int j = 0; j < 8; j++) {
        int idx = t + j * 256;            // 2048 float4 reads
        int h = idx & 63;
        int kc = idx >> 6;                // 0..31
        int k = kc * 4;
        float4 w = (k < 64)
            ? *reinterpret_cast<const float4*>(Wl + h * 64 + k)
            : *reinterpret_cast<const float4*>(Wr + h * 64 + (k - 64));
        Bs[(k + 0) * 64 + h] = w.x;
        Bs[(k + 1) * 64 + h] = w.y;
        Bs[(k + 2) * 64 + h] = w.z;
        Bs[(k + 3) * 64 + h] = w.w;
    }
    if (t < 64) Bb[t] = bias[t];

    // Load A rows: [mean | xin], mean = agg/max(deg,1); optionally zero agg.
#pragma unroll
    for (int j = 0; j < 16; j++) {
        int idx = t + j * 256;            // 4096 float4 loads
        int r = idx >> 5, q = idx & 31;
        int grow = rowBase + r;
        float4 v;
        if (q < 16) {
            v = *reinterpret_cast<const float4*>(agg + (size_t)grow * H + q * 4);
            float inv = 1.0f / fmaxf(deg[grow], 1.0f);
            v.x *= inv; v.y *= inv; v.z *= inv; v.w *= inv;
            if (ZERO) {
                float4 z = make_float4(0.f, 0.f, 0.f, 0.f);
                *reinterpret_cast<float4*>(agg + (size_t)grow * H + q * 4) = z;
            }
        } else {
            v = *reinterpret_cast<const float4*>(xin + (size_t)grow * H + (q - 16) * 4);
        }
        *reinterpret_cast<float4*>(As + r * 128 + q * 4) = v;
    }
    __syncthreads();

    int tx = t & 15, ty = t >> 4;
    int c0 = tx * 4, r0 = ty * 8;

    ull acc[8][2];
    {
        ull b0 = *reinterpret_cast<const ull*>(Bb + c0);
        ull b1 = *reinterpret_cast<const ull*>(Bb + c0 + 2);
#pragma unroll
        for (int i = 0; i < 8; i++) { acc[i][0] = b0; acc[i][1] = b1; }
    }

#pragma unroll 2
    for (int k0 = 0; k0 < 128; k0 += 4) {
        ull b01[4], b23[4];
#pragma unroll
        for (int kk = 0; kk < 4; kk++) {
            const float* bp = Bs + (k0 + kk) * 64 + c0;
            b01[kk] = *reinterpret_cast<const ull*>(bp);
            b23[kk] = *reinterpret_cast<const ull*>(bp + 2);
        }
#pragma unroll
        for (int i = 0; i < 8; i++) {
            float4 a = *reinterpret_cast<const float4*>(As + (r0 + i) * 128 + k0);
            ull ax = pack2(a.x, a.x);
            fma2(acc[i][0], ax, b01[0]); fma2(acc[i][1], ax, b23[0]);
            ull ay = pack2(a.y, a.y);
            fma2(acc[i][0], ay, b01[1]); fma2(acc[i][1], ay, b23[1]);
            ull az = pack2(a.z, a.z);
            fma2(acc[i][0], az, b01[2]); fma2(acc[i][1], az, b23[2]);
            ull aw = pack2(a.w, a.w);
            fma2(acc[i][0], aw, b01[3]); fma2(acc[i][1], aw, b23[3]);
        }
    }

#pragma unroll
    for (int i = 0; i < 8; i++) {
        float2 p0 = unpack2(acc[i][0]);
        float2 p1 = unpack2(acc[i][1]);
        float4 o = make_float4(p0.x, p0.y, p1.x, p1.y);
        if (RELU) {
            o.x = fmaxf(o.x, 0.f); o.y = fmaxf(o.y, 0.f);
            o.z = fmaxf(o.z, 0.f); o.w = fmaxf(o.w, 0.f);
        }
        *reinterpret_cast<float4*>(xout + (size_t)(rowBase + r0 + i) * H + c0) = o;
    }
}

// ---------------- epilogue: out[e] = dot(x2[u], x2[N_USERS+m]) ----------------
__global__ void edgedot_kernel(const float* __restrict__ x2,
                               const int* __restrict__ lu,
                               const int* __restrict__ lm,
                               float* __restrict__ out, int EL) {
    long long t = (long long)blockIdx.x * blockDim.x + threadIdx.x;
    int e = (int)(t >> 4);
    if (e >= EL) return;
    int part = (int)t & 15;
    int u = lu[e];
    int m = lm[e];
    float4 a = *reinterpret_cast<const float4*>(x2 + (size_t)u * H + part * 4);
    float4 b = *reinterpret_cast<const float4*>(x2 + (size_t)(N_USERS + m) * H + part * 4);
    float s = a.x * b.x + a.y * b.y + a.z * b.z + a.w * b.w;
#pragma unroll
    for (int off = 8; off > 0; off >>= 1)
        s += __shfl_down_sync(0xffffffffu, s, off, 16);
    if (part == 0) out[e] = s;
}

extern "C" void kernel_launch(void* const* d_in, const int* in_sizes, int n_in,
                              void* d_out, int out_size) {
    const float* movie_x   = (const float*)d_in[0];
    const float* user_emb  = (const float*)d_in[1];
    const float* movie_emb = (const float*)d_in[2];
    const float* lin_W     = (const float*)d_in[3];
    const float* lin_b     = (const float*)d_in[4];
    const float* W1l       = (const float*)d_in[5];
    const float* b1        = (const float*)d_in[6];
    const float* W1r       = (const float*)d_in[7];
    const float* W2l       = (const float*)d_in[8];
    const float* b2        = (const float*)d_in[9];
    const float* W2r       = (const float*)d_in[10];
    const int* edge_index  = (const int*)d_in[11];   // int32: JAX x64 is disabled
    const int* ell         = (const int*)d_in[12];   // int32
    int E  = in_sizes[11] / 2;
    int EL = in_sizes[12] / 2;
    float* out = (float*)d_out;

    float *x0, *x1, *agg, *deg;
    cudaGetSymbolAddress((void**)&x0, g_x0);
    cudaGetSymbolAddress((void**)&x1, g_x1);
    cudaGetSymbolAddress((void**)&agg, g_agg);
    cudaGetSymbolAddress((void**)&deg, g_deg);

    const int smem = COMB_SMEM_FLOATS * (int)sizeof(float);
    cudaFuncSetAttribute(combine_kernel<true, true>,
                         cudaFuncAttributeMaxDynamicSharedMemorySize, smem);
    cudaFuncSetAttribute(combine_kernel<false, false>,
                         cudaFuncAttributeMaxDynamicSharedMemorySize, smem);

    // init
    cudaMemsetAsync(agg, 0, sizeof(float) * (size_t)NN * H);
    cudaMemsetAsync(deg, 0, sizeof(float) * NN);
    cudaMemcpyAsync(x0, user_emb, sizeof(float) * (size_t)N_USERS * H,
                    cudaMemcpyDeviceToDevice);
    movie_init_kernel<<<N_MOVIES / 4, 256>>>(movie_x, lin_W, lin_b, movie_emb, x0);
    deg_kernel<<<(E + 255) / 256, 256>>>(edge_index + E, deg, E);

    long long scat_threads = (long long)E * 16;
    int scat_blocks = (int)((scat_threads + 255) / 256);
    int comb_blocks = (NN + COMB_ROWS - 1) / COMB_ROWS;   // 2188

    // layer 1
    scatter_kernel<<<scat_blocks, 256>>>(edge_index, edge_index + E, x0, agg, E);
    combine_kernel<true, true><<<comb_blocks, 256, smem>>>(x0, agg, deg, W1l, b1, W1r, x1);

    // layer 2 (agg was re-zeroed by combine_kernel<...,true>)
    scatter_kernel<<<scat_blocks, 256>>>(edge_index, edge_index + E, x1, agg, E);
    combine_kernel<false, false><<<comb_blocks, 256, smem>>>(x1, agg, deg, W2l, b2, W2r, x0);

    // epilogue
    long long dot_threads = (long long)EL * 16;
    int dot_blocks = (int)((dot_threads + 255) / 256);
    edgedot_kernel<<<dot_blocks, 256>>>(x0, ell, ell + EL, out, EL);
}

// round 7
// speedup vs baseline: 1.1139x; 1.1139x over previous
#include <cuda_runtime.h>
#include <cuda_bf16.h>
#include <cstdint>

#define N_USERS 200000
#define N_MOVIES 80000
#define NN 280000            // N_USERS + N_MOVIES
#define H 64
#define FM 20

typedef unsigned long long ull;

// Scratch (device globals; allocation is forbidden). ~216 MB total.
__device__ float g_x0[(size_t)NN * H];
__device__ float g_x1[(size_t)NN * H];
__device__ float g_agg[(size_t)NN * H];
__device__ float g_deg[NN];

// ---------------- f32x2 packed-FMA helpers (Blackwell FFMA2) ----------------
__device__ __forceinline__ ull pack2(float a, float b) {
    ull r;
    asm("mov.b64 %0, {%1, %2};" : "=l"(r) : "f"(a), "f"(b));
    return r;
}
__device__ __forceinline__ void fma2(ull& d, ull a, ull b) {
    asm("fma.rn.f32x2 %0, %1, %2, %0;" : "+l"(d) : "l"(a), "l"(b));
}
__device__ __forceinline__ float2 unpack2(ull v) {
    float2 f;
    asm("mov.b64 {%0, %1}, %2;" : "=f"(f.x), "=f"(f.y) : "l"(v));
    return f;
}

// ---------------- movie feature init: x_movie = movie_x @ lin_W.T + lin_b + movie_emb ----
__global__ void movie_init_kernel(const float* __restrict__ movie_x,
                                  const float* __restrict__ lin_W,
                                  const float* __restrict__ lin_b,
                                  const float* __restrict__ movie_emb,
                                  float* __restrict__ x0) {
    int mlocal = threadIdx.x >> 6;
    int h = threadIdx.x & 63;
    int m = blockIdx.x * 4 + mlocal;
    __shared__ float mx[4][FM];
    int li = threadIdx.x;
    if (li < 4 * FM) {
        int mm = li / FM, ff = li % FM;
        mx[mm][ff] = movie_x[(size_t)(blockIdx.x * 4 + mm) * FM + ff];
    }
    __syncthreads();
    float s = lin_b[h];
#pragma unroll
    for (int f = 0; f < FM; f++) s += mx[mlocal][f] * lin_W[h * FM + f];
    x0[(size_t)(N_USERS + m) * H + h] = s + movie_emb[(size_t)m * H + h];
}

// ---------------- degree count (same for both layers) ----------------
__global__ void deg_kernel(const int* __restrict__ dst, float* __restrict__ deg, int E) {
    int e = blockIdx.x * blockDim.x + threadIdx.x;
    if (e < E) atomicAdd(deg + dst[e], 1.0f);
}

// ---------------- scatter: agg[dst] += x[src], vec4 global reductions ----------------
__global__ void scatter_kernel(const int* __restrict__ src,
                               const int* __restrict__ dst,
                               const float* __restrict__ x,
                               float* __restrict__ agg, int E) {
    long long t = (long long)blockIdx.x * blockDim.x + threadIdx.x;
    int e = (int)(t >> 4);
    if (e >= E) return;
    int part = (int)t & 15;
    int s = src[e];
    int d = dst[e];
    float4 v = *reinterpret_cast<const float4*>(x + (size_t)s * H + part * 4);
    float* p = agg + (size_t)d * H + part * 4;
    asm volatile("red.global.add.v4.f32 [%0], {%1,%2,%3,%4};"
                 :: "l"(p), "f"(v.x), "f"(v.y), "f"(v.z), "f"(v.w)
                 : "memory");
}

// ---------------- combine: xout = act( [agg/deg | xin] @ [Wl;Wr]^T + b ) ----------------
// Block: 64 rows x 64 cols (all of H), K=128. 256 threads, 4x4 thread tile.
// k-vectorized: A via LDS.128 (padded stride 132 -> bank-disjoint warp broadcasts),
// B via LDS.128 rows. f32x2 packed FMAs. ZERO: re-zero agg rows after reading.
#define ASTRIDE 132
#define COMB_SMEM_FLOATS (64 * ASTRIDE + 128 * 64 + 64)
template <bool RELU, bool ZERO>
__global__ void __launch_bounds__(256)
combine_kernel(const float* __restrict__ xin,
               float* agg,
               const float* __restrict__ deg,
               const float* __restrict__ Wl,
               const float* __restrict__ bias,
               const float* __restrict__ Wr,
               float* __restrict__ xout) {
    extern __shared__ float sh[];
    float* As = sh;                      // [64 rows][132] (128 used)
    float* Bs = sh + 64 * ASTRIDE;       // [128 k][64 h]
    float* Bb = Bs + 128 * 64;           // bias[64]
    int t = threadIdx.x;
    int rowBase = blockIdx.x * 64;

    // Load B = [Wl ; Wr] transposed into Bs[k][h].
#pragma unroll
    for (int j = 0; j < 8; j++) {
        int idx = t + j * 256;           // 2048 float4 reads
        int h = idx & 63;
        int k = (idx >> 6) * 4;          // 0..124
        float4 w = (k < 64)
            ? *reinterpret_cast<const float4*>(Wl + h * 64 + k)
            : *reinterpret_cast<const float4*>(Wr + h * 64 + (k - 64));
        Bs[(k + 0) * 64 + h] = w.x;
        Bs[(k + 1) * 64 + h] = w.y;
        Bs[(k + 2) * 64 + h] = w.z;
        Bs[(k + 3) * 64 + h] = w.w;
    }
    if (t < 64) Bb[t] = bias[t];

    // Load A rows: [mean | xin], mean = agg/max(deg,1); optionally zero agg.
#pragma unroll
    for (int j = 0; j < 8; j++) {
        int idx = t + j * 256;           // 2048 float4 loads
        int r = idx >> 5, q = idx & 31;
        int grow = rowBase + r;
        float4 v;
        if (q < 16) {
            v = *reinterpret_cast<const float4*>(agg + (size_t)grow * H + q * 4);
            float inv = 1.0f / fmaxf(deg[grow], 1.0f);
            v.x *= inv; v.y *= inv; v.z *= inv; v.w *= inv;
            if (ZERO) {
                float4 z = make_float4(0.f, 0.f, 0.f, 0.f);
                *reinterpret_cast<float4*>(agg + (size_t)grow * H + q * 4) = z;
            }
        } else {
            v = *reinterpret_cast<const float4*>(xin + (size_t)grow * H + (q - 16) * 4);
        }
        *reinterpret_cast<float4*>(As + r * ASTRIDE + q * 4) = v;
    }
    __syncthreads();

    int tx = t & 15, ty = t >> 4;
    int c0 = tx * 4, r0 = ty * 4;

    ull acc[4][2];
    {
        ull b0 = *reinterpret_cast<const ull*>(Bb + c0);
        ull b1 = *reinterpret_cast<const ull*>(Bb + c0 + 2);
#pragma unroll
        for (int i = 0; i < 4; i++) { acc[i][0] = b0; acc[i][1] = b1; }
    }

#pragma unroll 4
    for (int k0 = 0; k0 < 128; k0 += 4) {
        // B rows for 4 k-values (LDS.128 each; 256B contiguous per warp -> 2 wavefronts)
        float4 b[4];
#pragma unroll
        for (int kk = 0; kk < 4; kk++)
            b[kk] = *reinterpret_cast<const float4*>(Bs + (k0 + kk) * 64 + c0);
        // A: one LDS.128 per row, warp-broadcast, bank-disjoint via stride 132
#pragma unroll
        for (int i = 0; i < 4; i++) {
            float4 a = *reinterpret_cast<const float4*>(As + (r0 + i) * ASTRIDE + k0);
            ull ax = pack2(a.x, a.x);
            fma2(acc[i][0], ax, pack2(b[0].x, b[0].y));
            fma2(acc[i][1], ax, pack2(b[0].z, b[0].w));
            ull ay = pack2(a.y, a.y);
            fma2(acc[i][0], ay, pack2(b[1].x, b[1].y));
            fma2(acc[i][1], ay, pack2(b[1].z, b[1].w));
            ull az = pack2(a.z, a.z);
            fma2(acc[i][0], az, pack2(b[2].x, b[2].y));
            fma2(acc[i][1], az, pack2(b[2].z, b[2].w));
            ull aw = pack2(a.w, a.w);
            fma2(acc[i][0], aw, pack2(b[3].x, b[3].y));
            fma2(acc[i][1], aw, pack2(b[3].z, b[3].w));
        }
    }

#pragma unroll
    for (int i = 0; i < 4; i++) {
        float2 p0 = unpack2(acc[i][0]);
        float2 p1 = unpack2(acc[i][1]);
        float4 o = make_float4(p0.x, p0.y, p1.x, p1.y);
        if (RELU) {
            o.x = fmaxf(o.x, 0.f); o.y = fmaxf(o.y, 0.f);
            o.z = fmaxf(o.z, 0.f); o.w = fmaxf(o.w, 0.f);
        }
        *reinterpret_cast<float4*>(xout + (size_t)(rowBase + r0 + i) * H + c0) = o;
    }
}

// ---------------- epilogue: out[e] = dot(x2[u], x2[N_USERS+m]) ----------------
__global__ void edgedot_kernel(const float* __restrict__ x2,
                               const int* __restrict__ lu,
                               const int* __restrict__ lm,
                               float* __restrict__ out, int EL) {
    long long t = (long long)blockIdx.x * blockDim.x + threadIdx.x;
    int e = (int)(t >> 4);
    if (e >= EL) return;
    int part = (int)t & 15;
    int u = lu[e];
    int m = lm[e];
    float4 a = *reinterpret_cast<const float4*>(x2 + (size_t)u * H + part * 4);
    float4 b = *reinterpret_cast<const float4*>(x2 + (size_t)(N_USERS + m) * H + part * 4);
    float s = a.x * b.x + a.y * b.y + a.z * b.z + a.w * b.w;
#pragma unroll
    for (int off = 8; off > 0; off >>= 1)
        s += __shfl_down_sync(0xffffffffu, s, off, 16);
    if (part == 0) out[e] = s;
}

extern "C" void kernel_launch(void* const* d_in, const int* in_sizes, int n_in,
                              void* d_out, int out_size) {
    const float* movie_x   = (const float*)d_in[0];
    const float* user_emb  = (const float*)d_in[1];
    const float* movie_emb = (const float*)d_in[2];
    const float* lin_W     = (const float*)d_in[3];
    const float* lin_b     = (const float*)d_in[4];
    const float* W1l       = (const float*)d_in[5];
    const float* b1        = (const float*)d_in[6];
    const float* W1r       = (const float*)d_in[7];
    const float* W2l       = (const float*)d_in[8];
    const float* b2        = (const float*)d_in[9];
    const float* W2r       = (const float*)d_in[10];
    const int* edge_index  = (const int*)d_in[11];   // int32: JAX x64 is disabled
    const int* ell         = (const int*)d_in[12];   // int32
    int E  = in_sizes[11] / 2;
    int EL = in_sizes[12] / 2;
    float* out = (float*)d_out;

    float *x0, *x1, *agg, *deg;
    cudaGetSymbolAddress((void**)&x0, g_x0);
    cudaGetSymbolAddress((void**)&x1, g_x1);
    cudaGetSymbolAddress((void**)&agg, g_agg);
    cudaGetSymbolAddress((void**)&deg, g_deg);

    const int smem = COMB_SMEM_FLOATS * (int)sizeof(float);
    cudaFuncSetAttribute(combine_kernel<true, true>,
                         cudaFuncAttributeMaxDynamicSharedMemorySize, smem);
    cudaFuncSetAttribute(combine_kernel<false, false>,
                         cudaFuncAttributeMaxDynamicSharedMemorySize, smem);

    // init
    cudaMemsetAsync(agg, 0, sizeof(float) * (size_t)NN * H);
    cudaMemsetAsync(deg, 0, sizeof(float) * NN);
    cudaMemcpyAsync(x0, user_emb, sizeof(float) * (size_t)N_USERS * H,
                    cudaMemcpyDeviceToDevice);
    movie_init_kernel<<<N_MOVIES / 4, 256>>>(movie_x, lin_W, lin_b, movie_emb, x0);
    deg_kernel<<<(E + 255) / 256, 256>>>(edge_index + E, deg, E);

    long long scat_threads = (long long)E * 16;
    int scat_blocks = (int)((scat_threads + 255) / 256);

    // layer 1
    scatter_kernel<<<scat_blocks, 256>>>(edge_index, edge_index + E, x0, agg, E);
    combine_kernel<true, true><<<NN / 64, 256, smem>>>(x0, agg, deg, W1l, b1, W1r, x1);

    // layer 2 (agg was re-zeroed by combine_kernel<...,true>)
    scatter_kernel<<<scat_blocks, 256>>>(edge_index, edge_index + E, x1, agg, E);
    combine_kernel<false, false><<<NN / 64, 256, smem>>>(x1, agg, deg, W2l, b2, W2r, x0);

    // epilogue
    long long dot_threads = (long long)EL * 16;
    int dot_blocks = (int)((dot_threads + 255) / 256);
    edgedot_kernel<<<dot_blocks, 256>>>(x0, ell, ell + EL, out, EL);
}